// round 8
// baseline (speedup 1.0000x reference)
#include <cuda_runtime.h>
#include <math.h>

#define BB 128
#define SS 512
#define DD 768
#define PP 60
#define LL 5
#define KK 5
#define D4 (DD/4)            // 192
#define SEQ_OUT (KK*LL + SS) // 537
#define NCHUNK 16
#define CHUNK_S (SS/NCHUNK)  // 32
#define NT 192               // threads per block
#define NWARP (NT/32)        // 6

#define MAP_SCALE 0.1f
#define MAX_NORM (1.0f - 4e-3f)

// Output layout (float32, concatenated in reference return order)
#define N_PE    ((long long)BB*SEQ_OUT*DD)           // 52,801,536
#define OFF_RS  (N_PE)
#define OFF_IDX (OFF_RS + 1)
#define OFF_SIM (OFF_IDX + (long long)BB*KK)
#define OFF_SK  (OFF_SIM + (long long)BB*PP)

// Scratch (device globals -> no allocation). Counters zero-init and self-reset.
__device__ float g_xpart[BB*NCHUNK*DD];
__device__ float g_persum[BB];
__device__ int   g_cnt[BB];
__device__ int   g_done;

// ---------------------------------------------------------------------------
// Single fused kernel, register-capped so the cold epilogue does not tank the
// occupancy of the DRAM-bound copy (R7 lesson: 80 regs -> 31% occ -> 52% DRAM).
// __launch_bounds__(192, 8) => ~40 regs, 8 blocks/SM, 75% occupancy; the
// epilogue (128 of 2048 blocks) spills to local, which is noise.
// ---------------------------------------------------------------------------
__global__ void __launch_bounds__(NT, 8)
fused_kernel(const float4* __restrict__ xe,
             const float4* __restrict__ prompt,
             const float*  __restrict__ pkey,
             float* __restrict__ out) {
    int chunk = blockIdx.x, b = blockIdx.y, tid = threadIdx.x;
    int lane = tid & 31, warp = tid >> 5;

    // ---- phase 1: copy chunk + partial sum ----
    {
        const float4* src = xe + ((size_t)b * SS + (size_t)chunk * CHUNK_S) * D4 + tid;
        float4* dst = (float4*)out + ((size_t)b * SEQ_OUT + KK*LL + (size_t)chunk * CHUNK_S) * D4 + tid;
        float4 acc = make_float4(0.f, 0.f, 0.f, 0.f);
#pragma unroll 8
        for (int s = 0; s < CHUNK_S; s++) {
            float4 v = src[(size_t)s * D4];
            acc.x += v.x; acc.y += v.y; acc.z += v.z; acc.w += v.w;
            dst[(size_t)s * D4] = v;
        }
        ((float4*)g_xpart)[(b * NCHUNK + chunk) * D4 + tid] = acc;
    }

    // ---- release: every thread fences ITS OWN partial stores, then sync,
    //      then one thread publishes via the per-batch counter ----
    __threadfence();
    __syncthreads();
    __shared__ int elect;
    if (tid == 0) {
        int old = atomicAdd(&g_cnt[b], 1);
        elect = (old == NCHUNK - 1);
    }
    __syncthreads();
    if (!elect) return;
    if (tid == 0) g_cnt[b] = 0;   // self-reset for next graph replay

    __shared__ float qsh[DD];
    __shared__ float dsh[PP];     // distances
    __shared__ float csh[PP];     // key ball coefficients
    __shared__ float redsh[NWARP];
    __shared__ float x2sh;
    __shared__ int   ish[KK];

    // ---- q = map_to_ball(mean(x_embed[b])) ----
    float local = 0.f;
#pragma unroll
    for (int r = 0; r < 4; r++) {
        int d = tid + r * NT;
        float s = 0.f;
#pragma unroll
        for (int c = 0; c < NCHUNK; c++) s += g_xpart[(b * NCHUNK + c) * DD + d];
        s *= (1.0f / (float)SS);
        qsh[d] = s;               // hold mean in smem (keeps regs low)
        local += s * s;
    }
#pragma unroll
    for (int o = 16; o > 0; o >>= 1) local += __shfl_xor_sync(0xffffffffu, local, o);
    if (lane == 0) redsh[warp] = local;
    __syncthreads();
    if (tid == 0) {
        float ssq = 0.f;
#pragma unroll
        for (int i = 0; i < NWARP; i++) ssq += redsh[i];
        float inv = rsqrtf(fmaxf(ssq, 1e-12f));
        float n = sqrtf(fmaxf(ssq * inv * inv * (MAP_SCALE*MAP_SCALE), 1e-15f));
        float th = tanhf(n);
        float factor = (th > MAX_NORM) ? (MAX_NORM / th) : 1.0f;
        float nf = th * factor;
        x2sh = nf * nf;
        redsh[0] = inv * MAP_SCALE * (th / n) * factor;
    }
    __syncthreads();
    float coeffq = redsh[0];
#pragma unroll
    for (int r = 0; r < 4; r++) { int d = tid + r * NT; qsh[d] *= coeffq; }
    __syncthreads();
    float x2 = x2sh;

    // ---- per-key map-to-ball scalars + dot with q (warp per key) ----
    for (int p = warp; p < PP; p += NWARP) {
        const float* kr = pkey + (size_t)p * DD;
        float ssq = 0.f, dot = 0.f;
#pragma unroll 4
        for (int j = lane; j < DD; j += 32) {
            float kv = kr[j];
            ssq += kv * kv;
            dot += kv * qsh[j];
        }
#pragma unroll
        for (int o = 16; o > 0; o >>= 1) {
            ssq += __shfl_xor_sync(0xffffffffu, ssq, o);
            dot += __shfl_xor_sync(0xffffffffu, dot, o);
        }
        if (lane == 0) {
            float inv = rsqrtf(fmaxf(ssq, 1e-12f));
            float n = sqrtf(fmaxf(ssq * inv * inv * (MAP_SCALE*MAP_SCALE), 1e-15f));
            float th = tanhf(n);
            float factor = (th > MAX_NORM) ? (MAX_NORM / th) : 1.0f;
            float coeffk = inv * MAP_SCALE * (th / n) * factor;
            float nf = th * factor;
            float y2 = nf * nf;
            float xy = dot * coeffk;   // dot(q_ball, key_ball)
            float A   = 1.f - 2.f*xy + y2;
            float Bc  = 1.f - x2;
            float den = fmaxf(1.f - 2.f*xy + x2*y2, 1e-15f);
            float n2  = (A*A*x2 - 2.f*A*Bc*xy + Bc*Bc*y2) / (den*den);
            float nn  = sqrtf(fmaxf(n2, 1e-15f));
            nn = fminf(nn, 1.f - 1e-7f);
            float dist = 2.f * atanhf(nn);
            dsh[p] = dist;
            csh[p] = coeffk;
            out[OFF_SIM + (long long)b * PP + p] = -dist;
        }
    }
    __syncthreads();

    // ---- top-K (smallest dist), sorted idx, per-batch selected sum ----
    if (tid == 0) {
        int sel[KK];
        bool used[PP];
        for (int p = 0; p < PP; p++) used[p] = false;
        float sum = 0.f;
        for (int k = 0; k < KK; k++) {
            float best = 1e30f; int bi = 0;
            for (int p = 0; p < PP; p++)
                if (!used[p] && dsh[p] < best) { best = dsh[p]; bi = p; }
            used[bi] = true; sel[k] = bi; sum += best;
        }
        for (int i = 0; i < KK; i++)
            for (int j = i + 1; j < KK; j++)
                if (sel[j] < sel[i]) { int t2 = sel[i]; sel[i] = sel[j]; sel[j] = t2; }
        for (int k = 0; k < KK; k++) {
            ish[k] = sel[k];
            out[OFF_IDX + (long long)b * KK + k] = (float)sel[k];
        }
        g_persum[b] = sum;
    }
    __syncthreads();

    // ---- gather: prompt[idx] rows into prompted_embedding head ----
#pragma unroll
    for (int r = 0; r < KK*LL; r++) {
        int k = r / LL, l = r % LL;
        int j = ish[k];
        float4 v = prompt[((size_t)j * LL + l) * D4 + tid];
        ((float4*)out)[((size_t)b * SEQ_OUT + r) * D4 + tid] = v;
    }
    // ---- selected_key = raw_key * coeffk (odd base offset -> scalar stores) ----
#pragma unroll
    for (int k = 0; k < KK; k++) {
        int j = ish[k];
        float coeffk = csh[j];
        const float* kr = pkey + (size_t)j * DD;
        float* sk = out + OFF_SK + ((size_t)b * KK + k) * DD;
#pragma unroll 4
        for (int i = tid; i < DD; i += NT) sk[i] = kr[i] * coeffk;
    }

    // ---- final reduce_sim by the globally-last batch ----
    if (tid == 0) {
        __threadfence();   // covers this thread's g_persum store (single writer)
        int old = atomicAdd(&g_done, 1);
        if (old == BB - 1) {
            g_done = 0;    // self-reset for next graph replay
            float s = 0.f;
#pragma unroll 8
            for (int i = 0; i < BB; i++) s += g_persum[i];
            out[OFF_RS] = s * (1.0f / (float)BB);
        }
    }
}

extern "C" void kernel_launch(void* const* d_in, const int* in_sizes, int n_in,
                              void* d_out, int out_size) {
    const float* x_embed = nullptr;    // 128*512*768
    const float* prompt = nullptr;     // 60*5*768
    const float* prompt_key = nullptr; // 60*768
    for (int i = 0; i < n_in; i++) {
        if (in_sizes[i] == BB*SS*DD)        x_embed    = (const float*)d_in[i];
        else if (in_sizes[i] == PP*LL*DD)   prompt     = (const float*)d_in[i];
        else if (in_sizes[i] == PP*DD)      prompt_key = (const float*)d_in[i];
    }
    float* out = (float*)d_out;

    dim3 grid(NCHUNK, BB);
    fused_kernel<<<grid, NT>>>((const float4*)x_embed, (const float4*)prompt,
                               prompt_key, out);
}

// round 9
// speedup vs baseline: 1.3006x; 1.3006x over previous
#include <cuda_runtime.h>
#include <math.h>

#define BB 128
#define SS 512
#define DD 768
#define PP 60
#define LL 5
#define KK 5
#define D4 (DD/4)            // 192
#define SEQ_OUT (KK*LL + SS) // 537
#define NCHUNK 16
#define CHUNK_S (SS/NCHUNK)  // 32

#define MAP_SCALE 0.1f
#define MAX_NORM (1.0f - 4e-3f)

// Output layout (float32, concatenated in reference return order)
#define N_PE    ((long long)BB*SEQ_OUT*DD)           // 52,801,536
#define OFF_RS  (N_PE)
#define OFF_IDX (OFF_RS + 1)
#define OFF_SIM (OFF_IDX + (long long)BB*KK)
#define OFF_SK  (OFF_SIM + (long long)BB*PP)

// Scratch (device globals -> no allocation)
__device__ float g_xpart[BB*NCHUNK*DD];
__device__ float g_kcoef[PP];
__device__ float g_ky2[PP];
__device__ float g_persum[BB];
__device__ int   g_idx[BB*KK];

// ---------------------------------------------------------------------------
// Kernel 0: per-key map-to-ball scalars (coeffk, y2) — computed ONCE.
// grid PP, 192 threads (one float4 per thread).
// ---------------------------------------------------------------------------
__global__ void k0_key(const float4* __restrict__ pkey) {
    int p = blockIdx.x, tid = threadIdx.x;
    int lane = tid & 31, warp = tid >> 5;
    __shared__ float sh[6];
    float4 v = pkey[(size_t)p * D4 + tid];
    float ssq = v.x*v.x + v.y*v.y + v.z*v.z + v.w*v.w;
#pragma unroll
    for (int o = 16; o > 0; o >>= 1) ssq += __shfl_xor_sync(0xffffffffu, ssq, o);
    if (lane == 0) sh[warp] = ssq;
    __syncthreads();
    if (tid == 0) {
        float s = sh[0]+sh[1]+sh[2]+sh[3]+sh[4]+sh[5];
        float inv = rsqrtf(fmaxf(s, 1e-12f));
        float n = sqrtf(fmaxf(s * inv * inv * (MAP_SCALE*MAP_SCALE), 1e-15f));
        float th = tanhf(n);
        float factor = (th > MAX_NORM) ? (MAX_NORM / th) : 1.0f;
        float coeffk = inv * MAP_SCALE * (th / n) * factor;
        float nf = th * factor;
        g_kcoef[p] = coeffk;
        g_ky2[p]   = nf * nf;
    }
}

// ---------------------------------------------------------------------------
// Kernel 1: copy x_embed into prompted_embedding slot + per-chunk partial sums
// grid (NCHUNK, BB), 192 threads. EXACTLY the R3 code (32 regs, 75.9% DRAM).
// ---------------------------------------------------------------------------
__global__ void k1_copy_partial(const float4* __restrict__ xe, float4* __restrict__ out) {
    int chunk = blockIdx.x, b = blockIdx.y, t = threadIdx.x;
    const float4* src = xe + ((size_t)b * SS + (size_t)chunk * CHUNK_S) * D4 + t;
    float4* dst = out + ((size_t)b * SEQ_OUT + KK*LL + (size_t)chunk * CHUNK_S) * D4 + t;
    float4 acc = make_float4(0.f, 0.f, 0.f, 0.f);
#pragma unroll 8
    for (int s = 0; s < CHUNK_S; s++) {
        float4 v = src[(size_t)s * D4];
        acc.x += v.x; acc.y += v.y; acc.z += v.z; acc.w += v.w;
        dst[(size_t)s * D4] = v;
    }
    ((float4*)g_xpart)[(b * NCHUNK + chunk) * D4 + t] = acc;
}

// ---------------------------------------------------------------------------
// Kernel 2: per-batch mean -> map_to_ball -> 60 dot products -> distances ->
// similarity -> top-K -> idx. 128 blocks x 512 threads (16 warps).
// Key scalars precomputed by k0 -> dot-only inner loop, float4 everywhere.
// ---------------------------------------------------------------------------
__global__ void k2_dist_topk(const float4* __restrict__ pkey, float* __restrict__ out) {
    int b = blockIdx.x;
    int tid = threadIdx.x, lane = tid & 31, warp = tid >> 5;
    __shared__ float4 qsh4[D4];
    __shared__ float dsh[PP];
    __shared__ float redsh[16];
    __shared__ float x2sh;

    // ---- mean from partials (threads 0..383 handle 2 dims each as float2) ----
    float local = 0.f;
    if (tid < 384) {
        float sx = 0.f, sy = 0.f;
        const float2* pp = (const float2*)g_xpart;
#pragma unroll
        for (int c = 0; c < NCHUNK; c++) {
            float2 a = pp[(size_t)(b * NCHUNK + c) * (DD/2) + tid];
            sx += a.x; sy += a.y;
        }
        sx *= (1.0f / (float)SS);
        sy *= (1.0f / (float)SS);
        ((float2*)qsh4)[tid] = make_float2(sx, sy);
        local = sx*sx + sy*sy;
    }
#pragma unroll
    for (int o = 16; o > 0; o >>= 1) local += __shfl_xor_sync(0xffffffffu, local, o);
    if (lane == 0) redsh[warp] = local;
    __syncthreads();
    if (tid == 0) {
        float ssq = 0.f;
#pragma unroll
        for (int i = 0; i < 16; i++) ssq += redsh[i];
        float inv = rsqrtf(fmaxf(ssq, 1e-12f));
        float n = sqrtf(fmaxf(ssq * inv * inv * (MAP_SCALE*MAP_SCALE), 1e-15f));
        float th = tanhf(n);
        float factor = (th > MAX_NORM) ? (MAX_NORM / th) : 1.0f;
        float nf = th * factor;
        x2sh = nf * nf;
        redsh[0] = inv * MAP_SCALE * (th / n) * factor;
    }
    __syncthreads();
    float coeffq = redsh[0];
    if (tid < 384) {
        float2 q = ((float2*)qsh4)[tid];
        ((float2*)qsh4)[tid] = make_float2(q.x * coeffq, q.y * coeffq);
    }
    __syncthreads();
    float x2 = x2sh;

    // ---- warp-per-key dot (4 rounds of 16 warps over 60 keys) ----
    for (int p = warp; p < PP; p += 16) {
        const float4* kr = pkey + (size_t)p * D4;
        float dot = 0.f;
#pragma unroll
        for (int i = 0; i < 6; i++) {
            int j = lane + 32 * i;
            float4 kv = kr[j];
            float4 qv = qsh4[j];
            dot += kv.x*qv.x + kv.y*qv.y + kv.z*qv.z + kv.w*qv.w;
        }
#pragma unroll
        for (int o = 16; o > 0; o >>= 1) dot += __shfl_xor_sync(0xffffffffu, dot, o);
        if (lane == 0) {
            float coeffk = g_kcoef[p];
            float y2 = g_ky2[p];
            float xy = dot * coeffk;   // dot(q_ball, key_ball)
            float A   = 1.f - 2.f*xy + y2;
            float Bc  = 1.f - x2;
            float den = fmaxf(1.f - 2.f*xy + x2*y2, 1e-15f);
            float n2  = (A*A*x2 - 2.f*A*Bc*xy + Bc*Bc*y2) / (den*den);
            float nn  = sqrtf(fmaxf(n2, 1e-15f));
            nn = fminf(nn, 1.f - 1e-7f);
            float dist = 2.f * atanhf(nn);
            dsh[p] = dist;
            out[OFF_SIM + (long long)b * PP + p] = -dist;
        }
    }
    __syncthreads();

    // ---- top-K (smallest dist), sorted idx, per-batch selected sum ----
    if (tid == 0) {
        int sel[KK];
        bool used[PP];
        for (int p = 0; p < PP; p++) used[p] = false;
        float sum = 0.f;
        for (int k = 0; k < KK; k++) {
            float best = 1e30f; int bi = 0;
            for (int p = 0; p < PP; p++)
                if (!used[p] && dsh[p] < best) { best = dsh[p]; bi = p; }
            used[bi] = true; sel[k] = bi; sum += best;
        }
        for (int i = 0; i < KK; i++)
            for (int j = i + 1; j < KK; j++)
                if (sel[j] < sel[i]) { int t2 = sel[i]; sel[i] = sel[j]; sel[j] = t2; }
        for (int k = 0; k < KK; k++) {
            g_idx[b * KK + k] = sel[k];
            out[OFF_IDX + (long long)b * KK + k] = (float)sel[k];
        }
        g_persum[b] = sum;
    }
}

// ---------------------------------------------------------------------------
// Kernel 3: gather prompt[idx] + selected_key + reduce_sim.
// grid (KK*LL + KK = 30, BB), 192 threads; one output row per block.
// ---------------------------------------------------------------------------
__global__ void k3_gather(const float4* __restrict__ prompt,
                          const float* __restrict__ pkey,
                          float* __restrict__ out) {
    int r = blockIdx.x, b = blockIdx.y, t = threadIdx.x;
    if (r < KK*LL) {
        int k = r / LL, l = r % LL;
        int j = g_idx[b * KK + k];
        float4 v = prompt[((size_t)j * LL + l) * D4 + t];
        ((float4*)out)[((size_t)b * SEQ_OUT + r) * D4 + t] = v;
    } else {
        int k = r - KK*LL;
        int j = g_idx[b * KK + k];
        float coeffk = g_kcoef[j];
        const float* kr = pkey + (size_t)j * DD;
        float* sk = out + OFF_SK + ((size_t)b * KK + k) * DD;
#pragma unroll
        for (int i = t; i < DD; i += 192) sk[i] = kr[i] * coeffk;
    }
    if (r == 0 && b == 0 && t == 0) {
        float s = 0.f;
#pragma unroll 8
        for (int i = 0; i < BB; i++) s += g_persum[i];
        out[OFF_RS] = s * (1.0f / (float)BB);
    }
}

extern "C" void kernel_launch(void* const* d_in, const int* in_sizes, int n_in,
                              void* d_out, int out_size) {
    const float* x_embed = nullptr;    // 128*512*768
    const float* prompt = nullptr;     // 60*5*768
    const float* prompt_key = nullptr; // 60*768
    for (int i = 0; i < n_in; i++) {
        if (in_sizes[i] == BB*SS*DD)        x_embed    = (const float*)d_in[i];
        else if (in_sizes[i] == PP*LL*DD)   prompt     = (const float*)d_in[i];
        else if (in_sizes[i] == PP*DD)      prompt_key = (const float*)d_in[i];
    }
    float* out = (float*)d_out;

    k0_key<<<PP, D4>>>((const float4*)prompt_key);
    dim3 g1(NCHUNK, BB);
    k1_copy_partial<<<g1, D4>>>((const float4*)x_embed, (float4*)out);
    k2_dist_topk<<<BB, 512>>>((const float4*)prompt_key, out);
    dim3 g3(KK*LL + KK, BB);
    k3_gather<<<g3, D4>>>((const float4*)prompt, prompt_key, out);
}